// round 12
// baseline (speedup 1.0000x reference)
#include <cuda_runtime.h>
#include <cuda_fp16.h>
#include <math.h>

#define NATOMS 50000
#define NEDGES 800000
#define HC 64
#define NG 50
#define NL 6
#define NB 128
#define TBL 1024

#define DMAX 8.6625
#define TSTEP ((float)(DMAX / (double)(TBL - 1)))
#define TINV  ((float)((double)(TBL - 1) / DMAX))
#define GSTEP ((float)(10.0 / 49.0))
#define GCOEF ((float)(-0.5 / ((10.0 / 49.0) * (10.0 / 49.0))))
#define PI10  ((float)(3.14159265358979323846 / 10.0))

// scratch (device globals: allocation-free per harness rules)
__device__ float    g_h[NATOMS * HC];
__device__ __half   g_hj[NATOMS * HC];
__device__ unsigned g_aggh[NATOMS * HC / 2];   // bf16x2 per channel pair
__device__ __half   g_table[NL * TBL * HC];
__device__ float    g_pool[NB * HC];
__device__ int      g_cnt[NB];
__device__ float4   g_pos4[NATOMS];
// CSR
__device__ __align__(16) int g_rowptr[NATOMS + 16];
__device__ __align__(16) int g_cursor[NATOMS + 16];
__device__ unsigned long long g_meta[NEDGES];  // {fr:f16 | idx:u16 | src:u32}

// ---------------------------------------------------------------------------
__device__ __forceinline__ unsigned bf16x2_of(float lo, float hi) {
    unsigned r;
    asm("cvt.rn.bf16x2.f32 %0, %1, %2;" : "=r"(r) : "f"(hi), "f"(lo));
    return r;
}

__device__ __forceinline__ void mma_bf16(float d[4], unsigned a0, unsigned a1,
                                         unsigned a2, unsigned a3,
                                         unsigned b0, unsigned b1) {
    asm("mma.sync.aligned.m16n8k16.row.col.f32.bf16.bf16.f32 "
        "{%0,%1,%2,%3}, {%4,%5,%6,%7}, {%8,%9}, {%0,%1,%2,%3};"
        : "+f"(d[0]), "+f"(d[1]), "+f"(d[2]), "+f"(d[3])
        : "r"(a0), "r"(a1), "r"(a2), "r"(a3), "r"(b0), "r"(b1));
}

#define WT_STRIDE 72
__device__ __forceinline__ void pack_w(unsigned short* Wt, const float* __restrict__ W,
                                       int tid) {
    for (int i = tid; i < HC * HC; i += 256) {
        int k = i >> 6, nn = i & 63;
        float v = __ldg(&W[i]);
        unsigned short b;
        asm("cvt.rn.bf16.f32 %0, %1;" : "=h"(b) : "f"(v));
        Wt[nn * WT_STRIDE + k] = b;
    }
}

// ---------------------------------------------------------------------------
// zero cursor + pad pos into float4
__global__ void k_zero_cnt(const float* __restrict__ pos, int n) {
    int i = blockIdx.x * blockDim.x + threadIdx.x;
    if (i < n) {
        g_cursor[i] = 0;
        g_pos4[i] = make_float4(pos[3 * i], pos[3 * i + 1], pos[3 * i + 2], 0.f);
    }
}

// histogram of dst; block 0 also zeroes the pool accumulators
__global__ void k_hist(const int* __restrict__ dst, int E) {
    int e = blockIdx.x * blockDim.x + threadIdx.x;
    if (blockIdx.x == 0) {
        int tid = threadIdx.x;
        for (int i = tid; i < NB * 16; i += 256)
            ((float4*)g_pool)[i] = make_float4(0.f, 0.f, 0.f, 0.f);
        if (tid < NB) g_cnt[tid] = 0;
    }
    if (e < E) atomicAdd(&g_cursor[dst[e]], 1);
}

// single-block exclusive scan, 16 elements/thread
__global__ __launch_bounds__(1024) void k_scan(int n) {
    __shared__ int warpsum[32];
    __shared__ int carry_s;
    int tid = threadIdx.x, lane = tid & 31, w = tid >> 5;
    if (tid == 0) carry_s = 0;
    __syncthreads();
    for (int base = 0; base < n; base += 16384) {
        int i0 = base + tid * 16;
        int v[16];
#pragma unroll
        for (int c = 0; c < 4; c++) {
            int4 t;
            if (i0 + c * 4 + 3 < n) t = *(const int4*)&g_cursor[i0 + c * 4];
            else {
                t.x = (i0 + c * 4 + 0 < n) ? g_cursor[i0 + c * 4 + 0] : 0;
                t.y = (i0 + c * 4 + 1 < n) ? g_cursor[i0 + c * 4 + 1] : 0;
                t.z = (i0 + c * 4 + 2 < n) ? g_cursor[i0 + c * 4 + 2] : 0;
                t.w = (i0 + c * 4 + 3 < n) ? g_cursor[i0 + c * 4 + 3] : 0;
            }
            v[c * 4 + 0] = t.x; v[c * 4 + 1] = t.y; v[c * 4 + 2] = t.z; v[c * 4 + 3] = t.w;
        }
        int run[16];
        int tot = 0;
#pragma unroll
        for (int j = 0; j < 16; j++) { tot += v[j]; run[j] = tot; }
        int x = tot;
#pragma unroll
        for (int off = 1; off < 32; off <<= 1) {
            int y = __shfl_up_sync(0xffffffffu, x, off);
            if (lane >= off) x += y;
        }
        if (lane == 31) warpsum[w] = x;
        __syncthreads();
        if (w == 0) {
            int s = warpsum[lane];
#pragma unroll
            for (int off = 1; off < 32; off <<= 1) {
                int y = __shfl_up_sync(0xffffffffu, s, off);
                if (lane >= off) s += y;
            }
            warpsum[lane] = s;
        }
        __syncthreads();
        int woff = (w > 0) ? warpsum[w - 1] : 0;
        int eb = carry_s + woff + (x - tot);
#pragma unroll
        for (int j = 0; j < 16; j++) {
            int idx = i0 + j;
            if (idx < n) {
                int excl = eb + run[j] - v[j];
                g_rowptr[idx] = excl;
                g_cursor[idx] = excl;
            }
        }
        int total = warpsum[31];
        __syncthreads();
        if (tid == 0) carry_s += total;
        __syncthreads();
    }
    if (threadIdx.x == 0) g_rowptr[n] = carry_s;
}

// per-edge: distance -> packed meta, scattered into dst-sorted position
__global__ void k_scatter(const int* __restrict__ src, const int* __restrict__ dst, int E) {
    int e = blockIdx.x * blockDim.x + threadIdx.x;
    if (e >= E) return;
    int s = src[e], d = dst[e];
    float4 ps = __ldg(&g_pos4[s]);
    float4 pd = __ldg(&g_pos4[d]);
    float dx = ps.x - pd.x, dy = ps.y - pd.y, dz = ps.z - pd.z;
    float t = sqrtf(dx * dx + dy * dy + dz * dz) * TINV;
    int i = (int)t;
    if (i > TBL - 2) i = TBL - 2;
    float fr = t - (float)i;
    unsigned short fb = __half_as_ushort(__float2half_rn(fr));
    unsigned hi = (unsigned)i | ((unsigned)fb << 16);
    unsigned long long rec = ((unsigned long long)hi << 32) | (unsigned)s;
    int p = atomicAdd(&g_cursor[d], 1);
    g_meta[p] = rec;
}

// ---------------------------------------------------------------------------
// build table[l][i][f] = fp16( (tanh(gauss(x_i)@W1 + b1)@W2 + b2)[f] * cut(x_i) )
__global__ void k_build(const float* __restrict__ w1, const float* __restrict__ b1,
                        const float* __restrict__ w2, const float* __restrict__ b2) {
    int l = blockIdx.x / TBL;
    int i = blockIdx.x % TBL;
    int f = threadIdx.x;  // 64
    float x = (float)i * TSTEP;
    __shared__ float gs[NG];
    if (f < NG) {
        float dd = x - (float)f * GSTEP;
        gs[f] = expf(GCOEF * dd * dd);
    }
    __syncthreads();
    const float* W1 = w1 + l * NG * HC;
    float acc = b1[l * HC + f];
#pragma unroll
    for (int g = 0; g < NG; g++) acc += gs[g] * W1[g * HC + f];
    __shared__ float hid[HC];
    hid[f] = tanhf(acc);
    __syncthreads();
    const float* W2 = w2 + l * HC * HC;
    float w = b2[l * HC + f];
#pragma unroll 16
    for (int k = 0; k < HC; k++) w += hid[k] * W2[k * HC + f];
    float cut = 0.5f * (cosf(x * PI10) + 1.0f);
    g_table[(size_t)(l * TBL + i) * HC + f] = __float2half(w * cut);
}

// ---------------------------------------------------------------------------
// initial: h = embed[z]; hj = h @ W (bf16 MMA). 128 rows/block.
__global__ __launch_bounds__(256) void k_init(const float* __restrict__ W,
                                              const int* __restrict__ z,
                                              const float* __restrict__ embed, int n) {
    __shared__ unsigned short Wt[HC * WT_STRIDE];
    int tid = threadIdx.x;
    pack_w(Wt, W, tid);
    __syncthreads();

    int warp = tid >> 5, lane = tid & 31;
    int g = lane >> 2, t = lane & 3;
    int rbase = blockIdx.x * 128 + warp * 16;
    int row0 = rbase + g, row1 = row0 + 8;
    bool v0 = row0 < n, v1 = row1 < n;
    int rr0 = v0 ? row0 : 0, rr1 = v1 ? row1 : 0;
    const float* p0 = embed + (size_t)__ldg(&z[rr0]) * HC;
    const float* p1 = embed + (size_t)__ldg(&z[rr1]) * HC;

    float d[8][4];
#pragma unroll
    for (int nt = 0; nt < 8; nt++) { d[nt][0] = d[nt][1] = d[nt][2] = d[nt][3] = 0.f; }

#pragma unroll
    for (int kt = 0; kt < 4; kt++) {
        int kc = kt * 16 + t * 2;
        float2 f0 = *(const float2*)(p0 + kc);
        float2 f1 = *(const float2*)(p1 + kc);
        float2 f2 = *(const float2*)(p0 + kc + 8);
        float2 f3 = *(const float2*)(p1 + kc + 8);
        if (v0) { *(float2*)(g_h + (size_t)row0 * HC + kc) = f0;
                  *(float2*)(g_h + (size_t)row0 * HC + kc + 8) = f2; }
        if (v1) { *(float2*)(g_h + (size_t)row1 * HC + kc) = f1;
                  *(float2*)(g_h + (size_t)row1 * HC + kc + 8) = f3; }
        unsigned a0 = bf16x2_of(f0.x, f0.y);
        unsigned a1 = bf16x2_of(f1.x, f1.y);
        unsigned a2 = bf16x2_of(f2.x, f2.y);
        unsigned a3 = bf16x2_of(f3.x, f3.y);
#pragma unroll
        for (int nt = 0; nt < 8; nt++) {
            int nn = nt * 8 + g;
            unsigned b0 = *(const unsigned*)&Wt[nn * WT_STRIDE + kt * 16 + t * 2];
            unsigned b1 = *(const unsigned*)&Wt[nn * WT_STRIDE + kt * 16 + t * 2 + 8];
            mma_bf16(d[nt], a0, a1, a2, a3, b0, b1);
        }
    }
#pragma unroll
    for (int nt = 0; nt < 8; nt++) {
        int col = nt * 8 + t * 2;
        if (v0) {
            __half2 hh = __floats2half2_rn(d[nt][0], d[nt][1]);
            *(unsigned*)(g_hj + (size_t)row0 * HC + col) = *(unsigned*)&hh;
        }
        if (v1) {
            __half2 hh = __floats2half2_rn(d[nt][2], d[nt][3]);
            *(unsigned*)(g_hj + (size_t)row1 * HC + col) = *(unsigned*)&hh;
        }
    }
}

// ---------------------------------------------------------------------------
// fused layer update: h += agg@Wout + bias; if Wlin: hj = h_new @ Wlin.
// agg A-fragments are read directly as bf16x2 words (no cvt).
__global__ __launch_bounds__(256) void k_update(const float* __restrict__ Wout,
                                                const float* __restrict__ bias,
                                                const float* __restrict__ Wlin, int n) {
    __shared__ unsigned short Wt1[HC * WT_STRIDE];
    __shared__ unsigned short Wt2[HC * WT_STRIDE];
    int tid = threadIdx.x;
    pack_w(Wt1, Wout, tid);
    if (Wlin) pack_w(Wt2, Wlin, tid);
    __syncthreads();

    int warp = tid >> 5, lane = tid & 31;
    int g = lane >> 2, t = lane & 3;
    int rbase = blockIdx.x * 128 + warp * 16;
    int row0 = rbase + g, row1 = row0 + 8;
    bool v0 = row0 < n, v1 = row1 < n;
    int rr0 = v0 ? row0 : 0, rr1 = v1 ? row1 : 0;
    const unsigned* q0 = g_aggh + (size_t)rr0 * 32;
    const unsigned* q1 = g_aggh + (size_t)rr1 * 32;

    float d[8][4];
#pragma unroll
    for (int nt = 0; nt < 8; nt++) { d[nt][0] = d[nt][1] = d[nt][2] = d[nt][3] = 0.f; }

#pragma unroll
    for (int kt = 0; kt < 4; kt++) {
        unsigned a0 = __ldg(q0 + kt * 8 + t);
        unsigned a1 = __ldg(q1 + kt * 8 + t);
        unsigned a2 = __ldg(q0 + kt * 8 + t + 4);
        unsigned a3 = __ldg(q1 + kt * 8 + t + 4);
#pragma unroll
        for (int nt = 0; nt < 8; nt++) {
            int nn = nt * 8 + g;
            unsigned b0 = *(const unsigned*)&Wt1[nn * WT_STRIDE + kt * 16 + t * 2];
            unsigned b1 = *(const unsigned*)&Wt1[nn * WT_STRIDE + kt * 16 + t * 2 + 8];
            mma_bf16(d[nt], a0, a1, a2, a3, b0, b1);
        }
    }

    // epilogue: h_new = h_old + d + bias (kept in d[] for the second MMA)
#pragma unroll
    for (int nt = 0; nt < 8; nt++) {
        int col = nt * 8 + t * 2;
        float2 bv = *(const float2*)(bias + col);
        if (v0) {
            float2 rv = *(const float2*)(g_h + (size_t)row0 * HC + col);
            d[nt][0] += bv.x + rv.x;
            d[nt][1] += bv.y + rv.y;
            *(float2*)(g_h + (size_t)row0 * HC + col) = make_float2(d[nt][0], d[nt][1]);
        }
        if (v1) {
            float2 rv = *(const float2*)(g_h + (size_t)row1 * HC + col);
            d[nt][2] += bv.x + rv.x;
            d[nt][3] += bv.y + rv.y;
            *(float2*)(g_h + (size_t)row1 * HC + col) = make_float2(d[nt][2], d[nt][3]);
        }
    }

    if (!Wlin) return;

    // second MMA: hj = h_new @ Wlin; A fragments = D fragments of first MMA
    float d2[8][4];
#pragma unroll
    for (int nt = 0; nt < 8; nt++) { d2[nt][0] = d2[nt][1] = d2[nt][2] = d2[nt][3] = 0.f; }
#pragma unroll
    for (int kt = 0; kt < 4; kt++) {
        unsigned a0 = bf16x2_of(d[2 * kt][0], d[2 * kt][1]);
        unsigned a1 = bf16x2_of(d[2 * kt][2], d[2 * kt][3]);
        unsigned a2 = bf16x2_of(d[2 * kt + 1][0], d[2 * kt + 1][1]);
        unsigned a3 = bf16x2_of(d[2 * kt + 1][2], d[2 * kt + 1][3]);
#pragma unroll
        for (int nt = 0; nt < 8; nt++) {
            int nn = nt * 8 + g;
            unsigned b0 = *(const unsigned*)&Wt2[nn * WT_STRIDE + kt * 16 + t * 2];
            unsigned b1 = *(const unsigned*)&Wt2[nn * WT_STRIDE + kt * 16 + t * 2 + 8];
            mma_bf16(d2[nt], a0, a1, a2, a3, b0, b1);
        }
    }
#pragma unroll
    for (int nt = 0; nt < 8; nt++) {
        int col = nt * 8 + t * 2;
        if (v0) {
            __half2 hh = __floats2half2_rn(d2[nt][0], d2[nt][1]);
            *(unsigned*)(g_hj + (size_t)row0 * HC + col) = *(unsigned*)&hh;
        }
        if (v1) {
            __half2 hh = __floats2half2_rn(d2[nt][2], d2[nt][3]);
            *(unsigned*)(g_hj + (size_t)row1 * HC + col) = *(unsigned*)&hh;
        }
    }
}

// ---------------------------------------------------------------------------
// CSR gather, 16 thr/node (2-way split), 3-stage software pipeline:
//   stage A: rec[i+2] load (no deps)  stage B: table/hj loads for rec[i+1]
//   stage C: FMAs on loads of i  -> per-iter latency hidden.
__global__ __launch_bounds__(256) void k_edge(int l, int n) {
    int gid = blockIdx.x * blockDim.x + threadIdx.x;
    bool valid = gid < n * 16;
    int node = valid ? (gid >> 4) : 0;
    int sub = (gid >> 3) & 1, q = gid & 7;
    int beg = 0, end = 0;
    if (valid) { beg = g_rowptr[node]; end = g_rowptr[node + 1]; }
    const __half* tl = g_table + (size_t)l * TBL * HC;
    float acc[8];
#pragma unroll
    for (int j = 0; j < 8; j++) acc[j] = 0.f;

    int k = beg + sub;
    // prologue: current loads + next rec
    uint4 a, b, hv;
    float fr = 0.f;
    if (k < end) {
        unsigned long long rec = __ldg(&g_meta[k]);
        int s = (int)(unsigned)(rec & 0xffffffffull);
        unsigned hi = (unsigned)(rec >> 32);
        int i = (int)(hi & 0xffffu);
        fr = __half2float(__ushort_as_half((unsigned short)(hi >> 16)));
        a = __ldg((const uint4*)(tl + (size_t)i * HC) + q);
        b = __ldg((const uint4*)(tl + (size_t)(i + 1) * HC) + q);
        hv = __ldg((const uint4*)(g_hj + (size_t)s * HC) + q);
    }
    unsigned long long recN = (k + 2 < end) ? __ldg(&g_meta[k + 2]) : 0ull;

    for (; k < end; k += 2) {
        int k2 = k + 2, k3 = k + 4;
        unsigned long long recNN = (k3 < end) ? __ldg(&g_meta[k3]) : 0ull;
        uint4 a2, b2, hv2;
        float fr2 = 0.f;
        if (k2 < end) {
            int s2 = (int)(unsigned)(recN & 0xffffffffull);
            unsigned hi2 = (unsigned)(recN >> 32);
            int i2 = (int)(hi2 & 0xffffu);
            fr2 = __half2float(__ushort_as_half((unsigned short)(hi2 >> 16)));
            a2 = __ldg((const uint4*)(tl + (size_t)i2 * HC) + q);
            b2 = __ldg((const uint4*)(tl + (size_t)(i2 + 1) * HC) + q);
            hv2 = __ldg((const uint4*)(g_hj + (size_t)s2 * HC) + q);
        }
        const unsigned* aw = (const unsigned*)&a;
        const unsigned* bw = (const unsigned*)&b;
        const unsigned* hw = (const unsigned*)&hv;
#pragma unroll
        for (int wdi = 0; wdi < 4; wdi++) {
            float2 af = __half22float2(*(const __half2*)&aw[wdi]);
            float2 bf = __half22float2(*(const __half2*)&bw[wdi]);
            float2 hf = __half22float2(*(const __half2*)&hw[wdi]);
            acc[2 * wdi + 0] += hf.x * (af.x + fr * (bf.x - af.x));
            acc[2 * wdi + 1] += hf.y * (af.y + fr * (bf.y - af.y));
        }
        a = a2; b = b2; hv = hv2; fr = fr2; recN = recNN;
    }
    // combine sub=1 into sub=0 (8 lanes apart)
#pragma unroll
    for (int j = 0; j < 8; j++)
        acc[j] += __shfl_down_sync(0xffffffffu, acc[j], 8);

    if (valid && sub == 0) {
        uint4 pk;
        pk.x = bf16x2_of(acc[0], acc[1]);
        pk.y = bf16x2_of(acc[2], acc[3]);
        pk.z = bf16x2_of(acc[4], acc[5]);
        pk.w = bf16x2_of(acc[6], acc[7]);
        *(uint4*)&g_aggh[(size_t)node * 32 + q * 4] = pk;
    }
}

// ---------------------------------------------------------------------------
__global__ void k_pool(const int* __restrict__ batch, int n) {
    int gid = blockIdx.x * blockDim.x + threadIdx.x;
    if (gid >= n * 16) return;
    int node = gid >> 4, q = gid & 15;
    int b = batch[node];
    float4 hv = ((const float4*)g_h)[node * 16 + q];
    float* p = g_pool + b * HC + q * 4;
    asm volatile("red.global.add.v4.f32 [%0], {%1,%2,%3,%4};"
                 :: "l"(p), "f"(hv.x), "f"(hv.y), "f"(hv.z), "f"(hv.w) : "memory");
    if (q == 0) atomicAdd(&g_cnt[b], 1);
}

__global__ void k_final(const float* __restrict__ fc1w, const float* __restrict__ fc1b,
                        const float* __restrict__ fc2w, const float* __restrict__ fc2b,
                        float* __restrict__ out) {
    int b = threadIdx.x;  // 128
    float inv = 1.0f / fmaxf((float)g_cnt[b], 1.0f);
    float p[HC];
#pragma unroll
    for (int c = 0; c < HC; c++) p[c] = g_pool[b * HC + c] * inv;
    float acc2 = fc2b[0];
    for (int j = 0; j < 32; j++) {
        float a = fc1b[j];
#pragma unroll
        for (int k = 0; k < HC; k++) a += p[k] * fc1w[k * 32 + j];
        a = fmaxf(a, 0.0f);
        acc2 += a * fc2w[j];
    }
    out[b] = acc2;
}

// ---------------------------------------------------------------------------
extern "C" void kernel_launch(void* const* d_in, const int* in_sizes, int n_in,
                              void* d_out, int out_size) {
    const int*   z         = (const int*)d_in[0];
    const float* pos       = (const float*)d_in[1];
    const int*   batch     = (const int*)d_in[2];
    const int*   eidx      = (const int*)d_in[3];
    const float* embed     = (const float*)d_in[4];
    const float* mlp_w1    = (const float*)d_in[5];
    const float* mlp_b1    = (const float*)d_in[6];
    const float* mlp_w2    = (const float*)d_in[7];
    const float* mlp_b2    = (const float*)d_in[8];
    const float* lin_w     = (const float*)d_in[9];
    const float* lin_out_w = (const float*)d_in[10];
    const float* lin_out_b = (const float*)d_in[11];
    const float* fc1w      = (const float*)d_in[12];
    const float* fc1b      = (const float*)d_in[13];
    const float* fc2w      = (const float*)d_in[14];
    const float* fc2b      = (const float*)d_in[15];

    int n = in_sizes[0];
    int E = in_sizes[3] / 2;
    const int* src = eidx;
    const int* dst = eidx + E;

    // CSR build
    k_zero_cnt<<<(n + 255) / 256, 256>>>(pos, n);
    k_hist<<<(E + 255) / 256, 256>>>(dst, E);
    k_scan<<<1, 1024>>>(n);
    k_scatter<<<(E + 255) / 256, 256>>>(src, dst, E);

    k_build<<<NL * TBL, HC>>>(mlp_w1, mlp_b1, mlp_w2, mlp_b2);

    int g_blocks = (n + 127) / 128;
    int edge_blocks = (n * 16 + 255) / 256;

    k_init<<<g_blocks, 256>>>(lin_w, z, embed, n);
    for (int l = 0; l < NL; l++) {
        k_edge<<<edge_blocks, 256>>>(l, n);
        const float* Wlin_next = (l + 1 < NL) ? (lin_w + (size_t)(l + 1) * HC * HC) : nullptr;
        k_update<<<g_blocks, 256>>>(lin_out_w + (size_t)l * HC * HC,
                                    lin_out_b + (size_t)l * HC, Wlin_next, n);
    }

    k_pool<<<(n * 16 + 255) / 256, 256>>>(batch, n);
    k_final<<<1, NB>>>(fc1w, fc1b, fc2w, fc2b, (float*)d_out);
}

// round 13
// speedup vs baseline: 1.0582x; 1.0582x over previous
#include <cuda_runtime.h>
#include <cuda_fp16.h>
#include <math.h>

#define NATOMS 50000
#define NEDGES 800000
#define HC 64
#define NG 50
#define NL 6
#define NB 128
#define TBL 1024

#define DMAX 8.6625
#define TSTEP ((float)(DMAX / (double)(TBL - 1)))
#define TINV  ((float)((double)(TBL - 1) / DMAX))
#define GSTEP ((float)(10.0 / 49.0))
#define GCOEF ((float)(-0.5 / ((10.0 / 49.0) * (10.0 / 49.0))))
#define PI10  ((float)(3.14159265358979323846 / 10.0))

// scratch (device globals: allocation-free per harness rules)
__device__ float    g_h[NATOMS * HC];
__device__ __half   g_hj[NATOMS * HC];
__device__ unsigned g_aggh[NATOMS * HC / 2];   // bf16x2 per channel pair
__device__ __half   g_table[NL * TBL * HC];
__device__ float    g_pool[NB * HC];
__device__ int      g_cnt[NB];
__device__ float4   g_pos4[NATOMS];
// CSR
__device__ __align__(16) int g_rowptr[NATOMS + 16];
__device__ __align__(16) int g_cursor[NATOMS + 16];
__device__ unsigned long long g_meta[NEDGES];  // {fr:f16 | idx:u16 | src:u32}

// ---------------------------------------------------------------------------
__device__ __forceinline__ unsigned bf16x2_of(float lo, float hi) {
    unsigned r;
    asm("cvt.rn.bf16x2.f32 %0, %1, %2;" : "=r"(r) : "f"(hi), "f"(lo));
    return r;
}

__device__ __forceinline__ void mma_bf16(float d[4], unsigned a0, unsigned a1,
                                         unsigned a2, unsigned a3,
                                         unsigned b0, unsigned b1) {
    asm("mma.sync.aligned.m16n8k16.row.col.f32.bf16.bf16.f32 "
        "{%0,%1,%2,%3}, {%4,%5,%6,%7}, {%8,%9}, {%0,%1,%2,%3};"
        : "+f"(d[0]), "+f"(d[1]), "+f"(d[2]), "+f"(d[3])
        : "r"(a0), "r"(a1), "r"(a2), "r"(a3), "r"(b0), "r"(b1));
}

#define WT_STRIDE 72
__device__ __forceinline__ void pack_w(unsigned short* Wt, const float* __restrict__ W,
                                       int tid) {
    for (int i = tid; i < HC * HC; i += 256) {
        int k = i >> 6, nn = i & 63;
        float v = __ldg(&W[i]);
        unsigned short b;
        asm("cvt.rn.bf16.f32 %0, %1;" : "=h"(b) : "f"(v));
        Wt[nn * WT_STRIDE + k] = b;
    }
}

// ---------------------------------------------------------------------------
// zero cursor + pad pos into float4
__global__ void k_zero_cnt(const float* __restrict__ pos, int n) {
    int i = blockIdx.x * blockDim.x + threadIdx.x;
    if (i < n) {
        g_cursor[i] = 0;
        g_pos4[i] = make_float4(pos[3 * i], pos[3 * i + 1], pos[3 * i + 2], 0.f);
    }
}

// histogram of dst; block 0 also zeroes the pool accumulators
__global__ void k_hist(const int* __restrict__ dst, int E) {
    int e = blockIdx.x * blockDim.x + threadIdx.x;
    if (blockIdx.x == 0) {
        int tid = threadIdx.x;
        for (int i = tid; i < NB * 16; i += 256)
            ((float4*)g_pool)[i] = make_float4(0.f, 0.f, 0.f, 0.f);
        if (tid < NB) g_cnt[tid] = 0;
    }
    if (e < E) atomicAdd(&g_cursor[dst[e]], 1);
}

// single-block exclusive scan, 16 elements/thread
__global__ __launch_bounds__(1024) void k_scan(int n) {
    __shared__ int warpsum[32];
    __shared__ int carry_s;
    int tid = threadIdx.x, lane = tid & 31, w = tid >> 5;
    if (tid == 0) carry_s = 0;
    __syncthreads();
    for (int base = 0; base < n; base += 16384) {
        int i0 = base + tid * 16;
        int v[16];
#pragma unroll
        for (int c = 0; c < 4; c++) {
            int4 t;
            if (i0 + c * 4 + 3 < n) t = *(const int4*)&g_cursor[i0 + c * 4];
            else {
                t.x = (i0 + c * 4 + 0 < n) ? g_cursor[i0 + c * 4 + 0] : 0;
                t.y = (i0 + c * 4 + 1 < n) ? g_cursor[i0 + c * 4 + 1] : 0;
                t.z = (i0 + c * 4 + 2 < n) ? g_cursor[i0 + c * 4 + 2] : 0;
                t.w = (i0 + c * 4 + 3 < n) ? g_cursor[i0 + c * 4 + 3] : 0;
            }
            v[c * 4 + 0] = t.x; v[c * 4 + 1] = t.y; v[c * 4 + 2] = t.z; v[c * 4 + 3] = t.w;
        }
        int run[16];
        int tot = 0;
#pragma unroll
        for (int j = 0; j < 16; j++) { tot += v[j]; run[j] = tot; }
        int x = tot;
#pragma unroll
        for (int off = 1; off < 32; off <<= 1) {
            int y = __shfl_up_sync(0xffffffffu, x, off);
            if (lane >= off) x += y;
        }
        if (lane == 31) warpsum[w] = x;
        __syncthreads();
        if (w == 0) {
            int s = warpsum[lane];
#pragma unroll
            for (int off = 1; off < 32; off <<= 1) {
                int y = __shfl_up_sync(0xffffffffu, s, off);
                if (lane >= off) s += y;
            }
            warpsum[lane] = s;
        }
        __syncthreads();
        int woff = (w > 0) ? warpsum[w - 1] : 0;
        int eb = carry_s + woff + (x - tot);
#pragma unroll
        for (int j = 0; j < 16; j++) {
            int idx = i0 + j;
            if (idx < n) {
                int excl = eb + run[j] - v[j];
                g_rowptr[idx] = excl;
                g_cursor[idx] = excl;
            }
        }
        int total = warpsum[31];
        __syncthreads();
        if (tid == 0) carry_s += total;
        __syncthreads();
    }
    if (threadIdx.x == 0) g_rowptr[n] = carry_s;
}

// per-edge: distance -> packed meta, scattered into dst-sorted position
__global__ void k_scatter(const int* __restrict__ src, const int* __restrict__ dst, int E) {
    int e = blockIdx.x * blockDim.x + threadIdx.x;
    if (e >= E) return;
    int s = src[e], d = dst[e];
    float4 ps = __ldg(&g_pos4[s]);
    float4 pd = __ldg(&g_pos4[d]);
    float dx = ps.x - pd.x, dy = ps.y - pd.y, dz = ps.z - pd.z;
    float t = sqrtf(dx * dx + dy * dy + dz * dz) * TINV;
    int i = (int)t;
    if (i > TBL - 2) i = TBL - 2;
    float fr = t - (float)i;
    unsigned short fb = __half_as_ushort(__float2half_rn(fr));
    unsigned hi = (unsigned)i | ((unsigned)fb << 16);
    unsigned long long rec = ((unsigned long long)hi << 32) | (unsigned)s;
    int p = atomicAdd(&g_cursor[d], 1);
    g_meta[p] = rec;
}

// ---------------------------------------------------------------------------
// build table[l][i][f] = fp16( (tanh(gauss(x_i)@W1 + b1)@W2 + b2)[f] * cut(x_i) )
__global__ void k_build(const float* __restrict__ w1, const float* __restrict__ b1,
                        const float* __restrict__ w2, const float* __restrict__ b2) {
    int l = blockIdx.x / TBL;
    int i = blockIdx.x % TBL;
    int f = threadIdx.x;  // 64
    float x = (float)i * TSTEP;
    __shared__ float gs[NG];
    if (f < NG) {
        float dd = x - (float)f * GSTEP;
        gs[f] = expf(GCOEF * dd * dd);
    }
    __syncthreads();
    const float* W1 = w1 + l * NG * HC;
    float acc = b1[l * HC + f];
#pragma unroll
    for (int g = 0; g < NG; g++) acc += gs[g] * W1[g * HC + f];
    __shared__ float hid[HC];
    hid[f] = tanhf(acc);
    __syncthreads();
    const float* W2 = w2 + l * HC * HC;
    float w = b2[l * HC + f];
#pragma unroll 16
    for (int k = 0; k < HC; k++) w += hid[k] * W2[k * HC + f];
    float cut = 0.5f * (cosf(x * PI10) + 1.0f);
    g_table[(size_t)(l * TBL + i) * HC + f] = __float2half(w * cut);
}

// ---------------------------------------------------------------------------
// initial: h = embed[z]; hj = h @ W (bf16 MMA). 128 rows/block.
__global__ __launch_bounds__(256) void k_init(const float* __restrict__ W,
                                              const int* __restrict__ z,
                                              const float* __restrict__ embed, int n) {
    __shared__ unsigned short Wt[HC * WT_STRIDE];
    int tid = threadIdx.x;
    pack_w(Wt, W, tid);
    __syncthreads();

    int warp = tid >> 5, lane = tid & 31;
    int g = lane >> 2, t = lane & 3;
    int rbase = blockIdx.x * 128 + warp * 16;
    int row0 = rbase + g, row1 = row0 + 8;
    bool v0 = row0 < n, v1 = row1 < n;
    int rr0 = v0 ? row0 : 0, rr1 = v1 ? row1 : 0;
    const float* p0 = embed + (size_t)__ldg(&z[rr0]) * HC;
    const float* p1 = embed + (size_t)__ldg(&z[rr1]) * HC;

    float d[8][4];
#pragma unroll
    for (int nt = 0; nt < 8; nt++) { d[nt][0] = d[nt][1] = d[nt][2] = d[nt][3] = 0.f; }

#pragma unroll
    for (int kt = 0; kt < 4; kt++) {
        int kc = kt * 16 + t * 2;
        float2 f0 = *(const float2*)(p0 + kc);
        float2 f1 = *(const float2*)(p1 + kc);
        float2 f2 = *(const float2*)(p0 + kc + 8);
        float2 f3 = *(const float2*)(p1 + kc + 8);
        if (v0) { *(float2*)(g_h + (size_t)row0 * HC + kc) = f0;
                  *(float2*)(g_h + (size_t)row0 * HC + kc + 8) = f2; }
        if (v1) { *(float2*)(g_h + (size_t)row1 * HC + kc) = f1;
                  *(float2*)(g_h + (size_t)row1 * HC + kc + 8) = f3; }
        unsigned a0 = bf16x2_of(f0.x, f0.y);
        unsigned a1 = bf16x2_of(f1.x, f1.y);
        unsigned a2 = bf16x2_of(f2.x, f2.y);
        unsigned a3 = bf16x2_of(f3.x, f3.y);
#pragma unroll
        for (int nt = 0; nt < 8; nt++) {
            int nn = nt * 8 + g;
            unsigned b0 = *(const unsigned*)&Wt[nn * WT_STRIDE + kt * 16 + t * 2];
            unsigned b1 = *(const unsigned*)&Wt[nn * WT_STRIDE + kt * 16 + t * 2 + 8];
            mma_bf16(d[nt], a0, a1, a2, a3, b0, b1);
        }
    }
#pragma unroll
    for (int nt = 0; nt < 8; nt++) {
        int col = nt * 8 + t * 2;
        if (v0) {
            __half2 hh = __floats2half2_rn(d[nt][0], d[nt][1]);
            *(unsigned*)(g_hj + (size_t)row0 * HC + col) = *(unsigned*)&hh;
        }
        if (v1) {
            __half2 hh = __floats2half2_rn(d[nt][2], d[nt][3]);
            *(unsigned*)(g_hj + (size_t)row1 * HC + col) = *(unsigned*)&hh;
        }
    }
}

// ---------------------------------------------------------------------------
// fused layer update: h += agg@Wout + bias; if Wlin: hj = h_new @ Wlin.
// agg A-fragments are read directly as bf16x2 words (no cvt).
__global__ __launch_bounds__(256) void k_update(const float* __restrict__ Wout,
                                                const float* __restrict__ bias,
                                                const float* __restrict__ Wlin, int n) {
    __shared__ unsigned short Wt1[HC * WT_STRIDE];
    __shared__ unsigned short Wt2[HC * WT_STRIDE];
    int tid = threadIdx.x;
    pack_w(Wt1, Wout, tid);
    if (Wlin) pack_w(Wt2, Wlin, tid);
    __syncthreads();

    int warp = tid >> 5, lane = tid & 31;
    int g = lane >> 2, t = lane & 3;
    int rbase = blockIdx.x * 128 + warp * 16;
    int row0 = rbase + g, row1 = row0 + 8;
    bool v0 = row0 < n, v1 = row1 < n;
    int rr0 = v0 ? row0 : 0, rr1 = v1 ? row1 : 0;
    const unsigned* q0 = g_aggh + (size_t)rr0 * 32;
    const unsigned* q1 = g_aggh + (size_t)rr1 * 32;

    float d[8][4];
#pragma unroll
    for (int nt = 0; nt < 8; nt++) { d[nt][0] = d[nt][1] = d[nt][2] = d[nt][3] = 0.f; }

#pragma unroll
    for (int kt = 0; kt < 4; kt++) {
        unsigned a0 = __ldg(q0 + kt * 8 + t);
        unsigned a1 = __ldg(q1 + kt * 8 + t);
        unsigned a2 = __ldg(q0 + kt * 8 + t + 4);
        unsigned a3 = __ldg(q1 + kt * 8 + t + 4);
#pragma unroll
        for (int nt = 0; nt < 8; nt++) {
            int nn = nt * 8 + g;
            unsigned b0 = *(const unsigned*)&Wt1[nn * WT_STRIDE + kt * 16 + t * 2];
            unsigned b1 = *(const unsigned*)&Wt1[nn * WT_STRIDE + kt * 16 + t * 2 + 8];
            mma_bf16(d[nt], a0, a1, a2, a3, b0, b1);
        }
    }

    // epilogue: h_new = h_old + d + bias (kept in d[] for the second MMA)
#pragma unroll
    for (int nt = 0; nt < 8; nt++) {
        int col = nt * 8 + t * 2;
        float2 bv = *(const float2*)(bias + col);
        if (v0) {
            float2 rv = *(const float2*)(g_h + (size_t)row0 * HC + col);
            d[nt][0] += bv.x + rv.x;
            d[nt][1] += bv.y + rv.y;
            *(float2*)(g_h + (size_t)row0 * HC + col) = make_float2(d[nt][0], d[nt][1]);
        }
        if (v1) {
            float2 rv = *(const float2*)(g_h + (size_t)row1 * HC + col);
            d[nt][2] += bv.x + rv.x;
            d[nt][3] += bv.y + rv.y;
            *(float2*)(g_h + (size_t)row1 * HC + col) = make_float2(d[nt][2], d[nt][3]);
        }
    }

    if (!Wlin) return;

    // second MMA: hj = h_new @ Wlin; A fragments = D fragments of first MMA
    float d2[8][4];
#pragma unroll
    for (int nt = 0; nt < 8; nt++) { d2[nt][0] = d2[nt][1] = d2[nt][2] = d2[nt][3] = 0.f; }
#pragma unroll
    for (int kt = 0; kt < 4; kt++) {
        unsigned a0 = bf16x2_of(d[2 * kt][0], d[2 * kt][1]);
        unsigned a1 = bf16x2_of(d[2 * kt][2], d[2 * kt][3]);
        unsigned a2 = bf16x2_of(d[2 * kt + 1][0], d[2 * kt + 1][1]);
        unsigned a3 = bf16x2_of(d[2 * kt + 1][2], d[2 * kt + 1][3]);
#pragma unroll
        for (int nt = 0; nt < 8; nt++) {
            int nn = nt * 8 + g;
            unsigned b0 = *(const unsigned*)&Wt2[nn * WT_STRIDE + kt * 16 + t * 2];
            unsigned b1 = *(const unsigned*)&Wt2[nn * WT_STRIDE + kt * 16 + t * 2 + 8];
            mma_bf16(d2[nt], a0, a1, a2, a3, b0, b1);
        }
    }
#pragma unroll
    for (int nt = 0; nt < 8; nt++) {
        int col = nt * 8 + t * 2;
        if (v0) {
            __half2 hh = __floats2half2_rn(d2[nt][0], d2[nt][1]);
            *(unsigned*)(g_hj + (size_t)row0 * HC + col) = *(unsigned*)&hh;
        }
        if (v1) {
            __half2 hh = __floats2half2_rn(d2[nt][2], d2[nt][3]);
            *(unsigned*)(g_hj + (size_t)row1 * HC + col) = *(unsigned*)&hh;
        }
    }
}

// ---------------------------------------------------------------------------
// CSR gather: 16 threads per node (2-way edge split), shfl-combine, bf16 store.
__global__ __launch_bounds__(256) void k_edge(int l, int n) {
    int gid = blockIdx.x * blockDim.x + threadIdx.x;
    bool valid = gid < n * 16;
    int node = valid ? (gid >> 4) : 0;
    int sub = (gid >> 3) & 1, q = gid & 7;
    int beg = 0, end = 0;
    if (valid) { beg = g_rowptr[node]; end = g_rowptr[node + 1]; }
    const __half* tl = g_table + (size_t)l * TBL * HC;
    float acc[8];
#pragma unroll
    for (int j = 0; j < 8; j++) acc[j] = 0.f;

    for (int k = beg + sub; k < end; k += 2) {
        unsigned long long rec = __ldg(&g_meta[k]);
        int s = (int)(unsigned)(rec & 0xffffffffull);
        unsigned hi = (unsigned)(rec >> 32);
        int i = (int)(hi & 0xffffu);
        float fr = __half2float(__ushort_as_half((unsigned short)(hi >> 16)));
        uint4 a = __ldg((const uint4*)(tl + (size_t)i * HC) + q);
        uint4 b = __ldg((const uint4*)(tl + (size_t)(i + 1) * HC) + q);
        uint4 hv = __ldg((const uint4*)(g_hj + (size_t)s * HC) + q);
        const unsigned* aw = (const unsigned*)&a;
        const unsigned* bw = (const unsigned*)&b;
        const unsigned* hw = (const unsigned*)&hv;
#pragma unroll
        for (int wdi = 0; wdi < 4; wdi++) {
            float2 af = __half22float2(*(const __half2*)&aw[wdi]);
            float2 bf = __half22float2(*(const __half2*)&bw[wdi]);
            float2 hf = __half22float2(*(const __half2*)&hw[wdi]);
            acc[2 * wdi + 0] += hf.x * (af.x + fr * (bf.x - af.x));
            acc[2 * wdi + 1] += hf.y * (af.y + fr * (bf.y - af.y));
        }
    }
    // combine sub=1 into sub=0 (8 lanes apart)
#pragma unroll
    for (int j = 0; j < 8; j++)
        acc[j] += __shfl_down_sync(0xffffffffu, acc[j], 8);

    if (valid && sub == 0) {
        uint4 pk;
        pk.x = bf16x2_of(acc[0], acc[1]);
        pk.y = bf16x2_of(acc[2], acc[3]);
        pk.z = bf16x2_of(acc[4], acc[5]);
        pk.w = bf16x2_of(acc[6], acc[7]);
        *(uint4*)&g_aggh[(size_t)node * 32 + q * 4] = pk;
    }
}

// ---------------------------------------------------------------------------
__global__ void k_pool(const int* __restrict__ batch, int n) {
    int gid = blockIdx.x * blockDim.x + threadIdx.x;
    if (gid >= n * 16) return;
    int node = gid >> 4, q = gid & 15;
    int b = batch[node];
    float4 hv = ((const float4*)g_h)[node * 16 + q];
    float* p = g_pool + b * HC + q * 4;
    asm volatile("red.global.add.v4.f32 [%0], {%1,%2,%3,%4};"
                 :: "l"(p), "f"(hv.x), "f"(hv.y), "f"(hv.z), "f"(hv.w) : "memory");
    if (q == 0) atomicAdd(&g_cnt[b], 1);
}

__global__ void k_final(const float* __restrict__ fc1w, const float* __restrict__ fc1b,
                        const float* __restrict__ fc2w, const float* __restrict__ fc2b,
                        float* __restrict__ out) {
    int b = threadIdx.x;  // 128
    float inv = 1.0f / fmaxf((float)g_cnt[b], 1.0f);
    float p[HC];
#pragma unroll
    for (int c = 0; c < HC; c++) p[c] = g_pool[b * HC + c] * inv;
    float acc2 = fc2b[0];
    for (int j = 0; j < 32; j++) {
        float a = fc1b[j];
#pragma unroll
        for (int k = 0; k < HC; k++) a += p[k] * fc1w[k * 32 + j];
        a = fmaxf(a, 0.0f);
        acc2 += a * fc2w[j];
    }
    out[b] = acc2;
}

// ---------------------------------------------------------------------------
extern "C" void kernel_launch(void* const* d_in, const int* in_sizes, int n_in,
                              void* d_out, int out_size) {
    const int*   z         = (const int*)d_in[0];
    const float* pos       = (const float*)d_in[1];
    const int*   batch     = (const int*)d_in[2];
    const int*   eidx      = (const int*)d_in[3];
    const float* embed     = (const float*)d_in[4];
    const float* mlp_w1    = (const float*)d_in[5];
    const float* mlp_b1    = (const float*)d_in[6];
    const float* mlp_w2    = (const float*)d_in[7];
    const float* mlp_b2    = (const float*)d_in[8];
    const float* lin_w     = (const float*)d_in[9];
    const float* lin_out_w = (const float*)d_in[10];
    const float* lin_out_b = (const float*)d_in[11];
    const float* fc1w      = (const float*)d_in[12];
    const float* fc1b      = (const float*)d_in[13];
    const float* fc2w      = (const float*)d_in[14];
    const float* fc2b      = (const float*)d_in[15];

    int n = in_sizes[0];
    int E = in_sizes[3] / 2;
    const int* src = eidx;
    const int* dst = eidx + E;

    // CSR build
    k_zero_cnt<<<(n + 255) / 256, 256>>>(pos, n);
    k_hist<<<(E + 255) / 256, 256>>>(dst, E);
    k_scan<<<1, 1024>>>(n);
    k_scatter<<<(E + 255) / 256, 256>>>(src, dst, E);

    k_build<<<NL * TBL, HC>>>(mlp_w1, mlp_b1, mlp_w2, mlp_b2);

    int g_blocks = (n + 127) / 128;
    int edge_blocks = (n * 16 + 255) / 256;

    k_init<<<g_blocks, 256>>>(lin_w, z, embed, n);
    for (int l = 0; l < NL; l++) {
        k_edge<<<edge_blocks, 256>>>(l, n);
        const float* Wlin_next = (l + 1 < NL) ? (lin_w + (size_t)(l + 1) * HC * HC) : nullptr;
        k_update<<<g_blocks, 256>>>(lin_out_w + (size_t)l * HC * HC,
                                    lin_out_b + (size_t)l * HC, Wlin_next, n);
    }

    k_pool<<<(n * 16 + 255) / 256, 256>>>(batch, n);
    k_final<<<1, NB>>>(fc1w, fc1b, fc2w, fc2b, (float*)d_out);
}